// round 3
// baseline (speedup 1.0000x reference)
#include <cuda_runtime.h>

constexpr int NB=4, NG=1024, NC=1024, NQ=256, FF=512, HH=8, DD=64;

constexpr size_t SZ_GF=(size_t)NB*NG*FF;            // 2,097,152
constexpr size_t SZ_QF=(size_t)NB*NQ*FF;            // 524,288
constexpr size_t O_G0=0;
constexpr size_t O_C0=O_G0+SZ_GF;
constexpr size_t O_Q0=O_C0+SZ_GF;
constexpr size_t O_G1=O_Q0+SZ_QF;
constexpr size_t O_GS=O_G1+SZ_GF;
constexpr size_t O_PJQ=O_GS+SZ_GF;
constexpr size_t O_PJK=O_PJQ+SZ_GF;
constexpr size_t O_AGG=O_PJK+SZ_GF;
constexpr size_t O_P1=O_AGG+SZ_GF;
constexpr size_t O_EQ=O_P1+SZ_GF;
constexpr size_t O_EK=O_EQ+32768;
constexpr size_t O_CM=O_EK+32768;
constexpr size_t O_CS=O_CM+32768;
constexpr size_t O_PM=O_CS+32768;
constexpr size_t O_PS=O_PM+262144;
constexpr size_t O_WT=O_PS+262144;
constexpr size_t O_BGC=O_WT+(size_t)3*2*512*512;
constexpr size_t O_BGQ=O_BGC+131072;
constexpr size_t O_PB=O_BGQ+32768;
constexpr size_t S_TOT=O_PB+(size_t)NB*HH*NG*NC;

__device__ float d_scratch[S_TOT];

// ---- bit-pack adjacency (int32 0/1 -> 1 bit) ----
__global__ void bitpack_k(const int* __restrict__ adj, unsigned* __restrict__ bits, int nwords){
    int w=blockIdx.x*256+threadIdx.x; if(w>=nwords) return;
    const int* p=adj+(size_t)w*32; unsigned v=0;
    #pragma unroll
    for(int i=0;i<32;i++) v|=(p[i]>0?1u:0u)<<i;
    bits[w]=v;
}

// ---- W [L,H,F,D] -> Wt [L,F,H*D] ----
__global__ void repack_k(const float* __restrict__ W, float* __restrict__ out, int total){
    int i=blockIdx.x*256+threadIdx.x; if(i>=total) return;
    int d=i&63, f=(i>>6)&511, h=(i>>15)&7, l=i>>18;
    out[((size_t)(l*FF+f))*512+h*64+d]=W[i];
}

// ---- e[b,h,n] = dot(X[b,n,h*64:+64], a[h,:]) ----
__global__ void dot_a_k(const float* __restrict__ X, const float* __restrict__ a,
                        float* __restrict__ out, int N){
    int idx=blockIdx.x*256+threadIdx.x; if(idx>=NB*HH*N) return;
    int n=idx%N, h=(idx/N)%HH, b=idx/(N*HH);
    const float* xp=X+((size_t)(b*N+n))*FF+h*DD;
    const float* ap=a+h*DD;
    float s=0.f;
    #pragma unroll
    for(int i=0;i<DD;i+=4){
        float4 xv=*(const float4*)(xp+i); float4 av=*(const float4*)(ap+i);
        s+=xv.x*av.x+xv.y*av.y+xv.z*av.z+xv.w*av.w;
    }
    out[idx]=s;
}

// ---- column softmax stats (over query axis n), chunked by 128 queries ----
// orient 0: bit(n,m)=bits[b][n][m]   orient 1: bit(n,m)=bits[b][m][n]
__global__ void colstats_k(const float* __restrict__ eq, const float* __restrict__ ek,
                           const unsigned* __restrict__ bits, float* __restrict__ pmax,
                           float* __restrict__ psum, int Nn, int Mm, int nch, int orient, int bld){
    __shared__ float s_eq[128];
    int tid=threadIdx.x, m=blockIdx.x*128+tid, chunk=blockIdx.y, bh=blockIdx.z, b=bh/HH;
    int n0=chunk*128;
    const unsigned* bb=bits+(size_t)b*NG*bld;
    float ekv=ek[bh*Mm+m];
    s_eq[tid]=eq[bh*Nn+n0+tid];
    __syncthreads();
    float mx=-3.0e38f, s=0.f;
    if(orient==1){
        unsigned w=0;
        for(int nn=0;nn<128;nn++){
            int n=n0+nn;
            if((n&31)==0) w=bb[(size_t)m*bld+(n>>5)];
            if((w>>(n&31))&1u){ float v=s_eq[nn]+ekv; v=fmaxf(v,0.2f*v); mx=fmaxf(mx,v); }
        }
        for(int nn=0;nn<128;nn++){
            int n=n0+nn;
            if((n&31)==0) w=bb[(size_t)m*bld+(n>>5)];
            if((w>>(n&31))&1u){ float v=s_eq[nn]+ekv; v=fmaxf(v,0.2f*v); s+=__expf(v-mx); }
        }
    } else {
        int mw=m>>5, msh=m&31;
        for(int nn=0;nn<128;nn++){
            if((bb[(size_t)(n0+nn)*bld+mw]>>msh)&1u){ float v=s_eq[nn]+ekv; v=fmaxf(v,0.2f*v); mx=fmaxf(mx,v); }
        }
        for(int nn=0;nn<128;nn++){
            if((bb[(size_t)(n0+nn)*bld+mw]>>msh)&1u){ float v=s_eq[nn]+ekv; v=fmaxf(v,0.2f*v); s+=__expf(v-mx); }
        }
    }
    pmax[(size_t)(bh*Mm+m)*nch+chunk]=mx;
    psum[(size_t)(bh*Mm+m)*nch+chunk]=s;
}

__global__ void colmerge_k(const float* __restrict__ pmax, const float* __restrict__ psum,
                           float* __restrict__ cmax, float* __restrict__ cscale, int Mm, int nch){
    int idx=blockIdx.x*256+threadIdx.x; if(idx>=NB*HH*Mm) return;
    float mx=-3.0e38f;
    for(int c=0;c<nch;c++) mx=fmaxf(mx,pmax[(size_t)idx*nch+c]);
    float s=0.f;
    for(int c=0;c<nch;c++){
        float pm=pmax[(size_t)idx*nch+c];
        if(pm>-1.0e38f) s+=psum[(size_t)idx*nch+c]*__expf(pm-mx);
    }
    cmax[idx]=mx; cscale[idx]=(s>0.f)?(1.f/s):0.f;
}

// ---- P[bh][n][m] = bit ? exp(lrelu(eq+ek)-cmax[m])*cscale[m] : 0 ----
__global__ void pgen_k(const float* __restrict__ eq, const float* __restrict__ ek,
                       const float* __restrict__ cmax, const float* __restrict__ cscale,
                       const unsigned* __restrict__ bits, float* __restrict__ P,
                       int Nn, int Mm, int orient, int bld){
    size_t idx=(size_t)blockIdx.x*256+threadIdx.x;
    size_t total=(size_t)NB*HH*Nn*Mm; if(idx>=total) return;
    int m=(int)(idx%Mm); size_t r=idx/Mm;
    int n=(int)(r%Nn); int bh=(int)(r/Nn); int b=bh/HH;
    const unsigned* bb=bits+(size_t)b*NG*bld;
    unsigned bit;
    if(orient==1) bit=(bb[(size_t)m*bld+(n>>5)]>>(n&31))&1u;
    else          bit=(bb[(size_t)n*bld+(m>>5)]>>(m&31))&1u;
    float v=0.f;
    if(bit){
        float e=eq[bh*Nn+n]+ek[bh*Mm+m];
        e=fmaxf(e,0.2f*e);
        v=__expf(e-cmax[bh*Mm+m])*cscale[bh*Mm+m];
    }
    P[idx]=v;
}

// ---- SGEMM: C = A1@B1 (+ A2@B2); CTA 128x64, BK=16, 256thr, 8x4 micro ----
struct GP {
    int M,N,K1,K2,Hdiv;
    const float *A1,*B1,*A2,*B2;
    int lda1,ldb1,lda2,ldb2,ldc;
    float* C;
    const float *E1,*E2;
    long long sA_b,sA_h,sB_b,sB_h,sC_b,sC_h;
    const unsigned* bits; int bld; long long sBits_b;
};

template<int ASRC,int EPI>
__global__ void __launch_bounds__(256) gemm_k(GP p){
    __shared__ float As[16][132];
    __shared__ float Bs[16][68];
    const int t=threadIdx.x;
    const int m0=blockIdx.x*128, n0=blockIdx.y*64, z=blockIdx.z;
    const int zb=z/p.Hdiv, zh=z%p.Hdiv;
    const float* B1=p.B1+zb*p.sB_b+zh*p.sB_h;
    float* C=p.C+zb*p.sC_b+zh*p.sC_h;
    const float* A1=nullptr; const unsigned* bitsp=nullptr;
    if(ASRC==0) A1=p.A1+zb*p.sA_b+zh*p.sA_h;
    else        bitsp=p.bits+zb*p.sBits_b;
    const int tm=(t&15)*8, tn=(t>>4)*4;
    float acc[8][4]={};
    const int Ktot=p.K1+p.K2;

    for(int kk=0;kk<Ktot;kk+=16){
        if(ASRC==0){
            const float* Ap; int ldA,ko;
            if(kk<p.K1){Ap=A1; ldA=p.lda1; ko=kk;} else {Ap=p.A2; ldA=p.lda2; ko=kk-p.K1;}
            #pragma unroll
            for(int u=0;u<2;u++){
                int j=t*2+u, r=j>>2, kq=(j&3)*4;
                float4 v=*(const float4*)(Ap+(long long)(m0+r)*ldA+ko+kq);
                As[kq+0][r]=v.x; As[kq+1][r]=v.y; As[kq+2][r]=v.z; As[kq+3][r]=v.w;
            }
        } else {
            int k=t>>4, mg=t&15;
            unsigned w=bitsp[(long long)(kk+k)*p.bld+((unsigned)(m0+mg*8)>>5)];
            int sh=(mg*8)&31;
            #pragma unroll
            for(int c=0;c<8;c++) As[k][mg*8+c]=((w>>(sh+c))&1u)?1.f:0.f;
        }
        {
            const float* Bp; int ldB,ko;
            if(kk<p.K1){Bp=B1; ldB=p.ldb1; ko=kk;} else {Bp=p.B2; ldB=p.ldb2; ko=kk-p.K1;}
            int rk=t>>4, cq=(t&15)*4;
            float4 v=*(const float4*)(Bp+(long long)(ko+rk)*ldB+n0+cq);
            *(float4*)&Bs[rk][cq]=v;
        }
        __syncthreads();
        #pragma unroll
        for(int k=0;k<16;k++){
            float4 a0=*(const float4*)&As[k][tm];
            float4 a1v=*(const float4*)&As[k][tm+4];
            float4 bv=*(const float4*)&Bs[k][tn];
            float av[8]={a0.x,a0.y,a0.z,a0.w,a1v.x,a1v.y,a1v.z,a1v.w};
            float bb[4]={bv.x,bv.y,bv.z,bv.w};
            #pragma unroll
            for(int i=0;i<8;i++)
                #pragma unroll
                for(int j=0;j<4;j++) acc[i][j]=fmaf(av[i],bb[j],acc[i][j]);
        }
        __syncthreads();
    }
    #pragma unroll
    for(int i=0;i<8;i++){
        long long row=m0+tm+i;
        float* cp=C+row*p.ldc+n0+tn;
        float4 o;
        if(EPI==0){
            o=make_float4(acc[i][0],acc[i][1],acc[i][2],acc[i][3]);
        } else if(EPI==2){
            o.x=acc[i][0]>0.f?acc[i][0]:__expf(acc[i][0])-1.f;
            o.y=acc[i][1]>0.f?acc[i][1]:__expf(acc[i][1])-1.f;
            o.z=acc[i][2]>0.f?acc[i][2]:__expf(acc[i][2])-1.f;
            o.w=acc[i][3]>0.f?acc[i][3]:__expf(acc[i][3])-1.f;
        } else {
            float4 v1=*(const float4*)(p.E1+row*p.ldc+n0+tn);
            float4 v2=*(const float4*)(p.E2+row*p.ldc+n0+tn);
            float f;
            f=1.f/(1.f+__expf(-acc[i][0])); o.x=v2.x+f*(v1.x-v2.x);
            f=1.f/(1.f+__expf(-acc[i][1])); o.y=v2.y+f*(v1.y-v2.y);
            f=1.f/(1.f+__expf(-acc[i][2])); o.z=v2.z+f*(v1.z-v2.z);
            f=1.f/(1.f+__expf(-acc[i][3])); o.w=v2.w+f*(v1.w-v2.w);
        }
        *(float4*)cp=o;
    }
}

static void gemm_go(int asrc,int epi,const GP& p,int zc){
    dim3 g(p.M/128,p.N/64,zc);
    if(asrc==1)      gemm_k<1,0><<<g,256>>>(p);
    else if(epi==0)  gemm_k<0,0><<<g,256>>>(p);
    else if(epi==1)  gemm_k<0,1><<<g,256>>>(p);
    else             gemm_k<0,2><<<g,256>>>(p);
}

static void proj_go(const float* X,int rows,const float* Wt,float* out){
    GP p{}; p.M=rows; p.N=512; p.K1=512; p.Hdiv=1;
    p.A1=X; p.lda1=512; p.B1=Wt; p.ldb1=512; p.C=out; p.ldc=512;
    gemm_go(0,0,p,1);
}

static void fusion_go(const float* a,const float* bm,int rows,const float* W,const float* U,
                      const float* Wf,const float* Uf,float* P1,float* out){
    GP p{}; p.M=rows; p.N=512; p.K1=512; p.K2=512; p.Hdiv=1;
    p.A1=a; p.lda1=512; p.B1=W; p.ldb1=512;
    p.A2=bm; p.lda2=512; p.B2=U; p.ldb2=512;
    p.C=P1; p.ldc=512;
    gemm_go(0,0,p,1);
    p.B1=Wf; p.B2=Uf; p.C=out; p.E1=P1; p.E2=a;
    gemm_go(0,1,p,1);
}

static void attn_go(float* S,const float* q,int Nqq,const float* kv,int Nkv,
                    const float* Wt,const float* a1,const float* a2,
                    int orient,const unsigned* bits,int bld,float* agg){
    float *projQ=S+O_PJQ, *projK=S+O_PJK, *eq=S+O_EQ, *ek=S+O_EK;
    float *cm=S+O_CM, *cs=S+O_CS, *pm=S+O_PM, *ps=S+O_PS, *P=S+O_PB;
    proj_go(q,NB*Nqq,Wt,projQ);
    proj_go(kv,NB*Nkv,Wt,projK);
    { int tot=NB*HH*Nqq; dot_a_k<<<(tot+255)/256,256>>>(projQ,a1,eq,Nqq); }
    { int tot=NB*HH*Nkv; dot_a_k<<<(tot+255)/256,256>>>(projK,a2,ek,Nkv); }
    int nch=Nqq/128;
    { dim3 g(Nkv/128,nch,NB*HH); colstats_k<<<g,128>>>(eq,ek,bits,pm,ps,Nqq,Nkv,nch,orient,bld); }
    { int tot=NB*HH*Nkv; colmerge_k<<<(tot+255)/256,256>>>(pm,ps,cm,cs,Nkv,nch); }
    { size_t tot=(size_t)NB*HH*Nqq*Nkv;
      pgen_k<<<(unsigned)((tot+255)/256),256>>>(eq,ek,cm,cs,bits,P,Nqq,Nkv,orient,bld); }
    GP p{}; p.M=Nqq; p.N=64; p.K1=Nkv; p.Hdiv=HH;
    p.A1=P; p.lda1=Nkv; p.sA_b=(long long)HH*Nqq*Nkv; p.sA_h=(long long)Nqq*Nkv;
    p.B1=projK; p.ldb1=512; p.sB_b=(long long)Nkv*512; p.sB_h=64;
    p.C=agg; p.ldc=512; p.sC_b=(long long)Nqq*512; p.sC_h=64;
    gemm_go(0,2,p,NB*HH);
}

extern "C" void kernel_launch(void* const* d_in, const int* in_sizes, int n_in,
                              void* d_out, int out_size){
    float* S; cudaGetSymbolAddress((void**)&S, d_scratch);
    const float* in_g=(const float*)d_in[0];
    const float* in_c=(const float*)d_in[1];
    const float* in_q=(const float*)d_in[2];
    const int* adj_gc=(const int*)d_in[3];
    const int* adj_gq=(const int*)d_in[4];
    const float* aW[3]={(const float*)d_in[5],(const float*)d_in[8],(const float*)d_in[11]};
    const float* aa1[3]={(const float*)d_in[6],(const float*)d_in[9],(const float*)d_in[12]};
    const float* aa2[3]={(const float*)d_in[7],(const float*)d_in[10],(const float*)d_in[13]};
    const float* fW=(const float*)d_in[14];
    const float* fU=(const float*)d_in[15];
    const float* fWf=(const float*)d_in[16];
    const float* fUf=(const float*)d_in[17];
    float* out=(float*)d_out;

    unsigned* bgc=(unsigned*)(S+O_BGC);
    unsigned* bgq=(unsigned*)(S+O_BGQ);
    float* Wt=S+O_WT;
    float *gsame=S+O_GS, *agg=S+O_AGG, *P1=S+O_P1, *G1tmp=S+O_G1;

    bitpack_k<<<(NB*NG*NC/32+255)/256,256>>>(adj_gc,bgc,NB*NG*NC/32);
    bitpack_k<<<(NB*NG*NQ/32+255)/256,256>>>(adj_gq,bgq,NB*NG*NQ/32);
    for(int tp=0;tp<3;tp++){
        int tot=2*HH*FF*DD;
        repack_k<<<(tot+255)/256,256>>>(aW[tp],Wt+(size_t)tp*2*FF*512,tot);
    }

    for(int l=0;l<2;l++){
        const float *Gin,*Cin,*Qin; float *Gout,*Cout,*Qout;
        if(l==0){ Gin=in_g; Cin=in_c; Qin=in_q; Gout=S+O_G0; Cout=S+O_C0; Qout=S+O_Q0; }
        else    { Gin=S+O_G0; Cin=S+O_C0; Qin=S+O_Q0;
                  Gout=out; Cout=out+SZ_GF; Qout=out+2*SZ_GF; }
        const float* fWl=fW+(size_t)l*4*FF*FF;  const float* fUl=fU+(size_t)l*4*FF*FF;
        const float* fWfl=fWf+(size_t)l*4*FF*FF; const float* fUfl=fUf+(size_t)l*4*FF*FF;

        // 1) gloss_same = adj_gc^T @ gloss  (bitmask-A GEMM, batched over b)
        {
            GP p{}; p.M=NC; p.N=512; p.K1=NG; p.Hdiv=1;
            p.bits=bgc; p.bld=NC/32; p.sBits_b=(long long)NG*(NC/32);
            p.B1=Gin; p.ldb1=512; p.sB_b=(long long)NG*512;
            p.C=gsame; p.ldc=512; p.sC_b=(long long)NC*512;
            gemm_go(1,0,p,NB);
        }
        // 2) clip_1
        fusion_go(Cin,gsame,NB*NC, fWl+0*FF*FF,fUl+0*FF*FF,fWfl+0*FF*FF,fUfl+0*FF*FF, P1,Cout);
        // 3) clip_agg = attn(gloss, clip, adj_gc)
        attn_go(S,Gin,NG,Cin,NC, Wt+(size_t)(0*2+l)*FF*512, aa1[0]+l*HH*DD, aa2[0]+l*HH*DD,
                0,bgc,NC/32, agg);
        // 4) gloss_1
        fusion_go(Gin,agg,NB*NG, fWl+1*FF*FF,fUl+1*FF*FF,fWfl+1*FF*FF,fUfl+1*FF*FF, P1,G1tmp);
        // 5) gloss_agg = attn(question, gloss, adj_gq^T)
        attn_go(S,Qin,NQ,Gin,NG, Wt+(size_t)(1*2+l)*FF*512, aa1[1]+l*HH*DD, aa2[1]+l*HH*DD,
                1,bgq,NQ/32, agg);
        // 6) question_1
        fusion_go(Qin,agg,NB*NQ, fWl+2*FF*FF,fUl+2*FF*FF,fWfl+2*FF*FF,fUfl+2*FF*FF, P1,Qout);
        // 7) question_agg = attn(gloss, question, adj_gq)
        attn_go(S,Gin,NG,Qin,NQ, Wt+(size_t)(2*2+l)*FF*512, aa1[2]+l*HH*DD, aa2[2]+l*HH*DD,
                0,bgq,NQ/32, agg);
        // 8) gloss_2
        fusion_go(G1tmp,agg,NB*NG, fWl+3*FF*FF,fUl+3*FF*FF,fWfl+3*FF*FF,fUfl+3*FF*FF, P1,Gout);
    }
}

// round 5
// speedup vs baseline: 2.8130x; 2.8130x over previous
#include <cuda_runtime.h>
#include <cuda_bf16.h>
#include <cstdint>

constexpr int NB=4, NG=1024, NC=1024, NQ=256, FF=512, HH=8, DD=64;
constexpr size_t SZ_GF=(size_t)NB*NG*FF, SZ_QF=(size_t)NB*NQ*FF;
constexpr size_t O_G0=0,O_C0=O_G0+SZ_GF,O_Q0=O_C0+SZ_GF,O_G1=O_Q0+SZ_QF,O_GS=O_G1+SZ_GF;
constexpr size_t O_PJQ=O_GS+SZ_GF,O_PJK=O_PJQ+SZ_GF,O_AGG=O_PJK+SZ_GF,O_P1=O_AGG+SZ_GF;
constexpr size_t O_EQ=O_P1+SZ_GF,O_EK=O_EQ+32768,O_CM=O_EK+32768,O_CS=O_CM+32768;
constexpr size_t O_PM=O_CS+32768,O_PS=O_PM+262144,O_WT=O_PS+262144;
constexpr size_t O_BGC=O_WT+(size_t)3*2*512*512,O_BGQ=O_BGC+131072,O_PB=O_BGQ+32768;
constexpr size_t S_TOT=O_PB+(size_t)NB*HH*NG*NC;
__device__ float d_scratch[S_TOT];

__global__ void bitpack_k(const int* __restrict__ adj, unsigned* __restrict__ bits, int nwords){
    int w=blockIdx.x*256+threadIdx.x; if(w>=nwords) return;
    const int* p=adj+(size_t)w*32; unsigned v=0;
    #pragma unroll
    for(int i=0;i<32;i++) v|=(p[i]>0?1u:0u)<<i;
    bits[w]=v;
}
__global__ void repack_k(const float* __restrict__ W, float* __restrict__ out, int total){
    int i=blockIdx.x*256+threadIdx.x; if(i>=total) return;
    int d=i&63, f=(i>>6)&511, h=(i>>15)&7, l=i>>18;
    out[((size_t)(l*FF+f))*512+h*64+d]=W[i];
}
__global__ void dot_a_k(const float* __restrict__ X, const float* __restrict__ a,
                        float* __restrict__ out, int N){
    int idx=blockIdx.x*256+threadIdx.x; if(idx>=NB*HH*N) return;
    int n=idx%N, h=(idx/N)%HH, b=idx/(N*HH);
    const float* xp=X+((size_t)(b*N+n))*FF+h*DD; const float* ap=a+h*DD;
    float s=0.f;
    #pragma unroll
    for(int i=0;i<DD;i+=4){
        float4 xv=*(const float4*)(xp+i); float4 av=*(const float4*)(ap+i);
        s+=xv.x*av.x+xv.y*av.y+xv.z*av.z+xv.w*av.w;
    }
    out[idx]=s;
}
__global__ void colstats_k(const float* __restrict__ eq, const float* __restrict__ ek,
                           const unsigned* __restrict__ bits, float* __restrict__ pmax,
                           float* __restrict__ psum, int Nn, int Mm, int nch, int orient, int bld){
    __shared__ float s_eq[128];
    int tid=threadIdx.x, m=blockIdx.x*128+tid, chunk=blockIdx.y, bh=blockIdx.z, b=bh/HH;
    int n0=chunk*128;
    const unsigned* bb=bits+(size_t)b*NG*bld;
    float ekv=ek[bh*Mm+m];
    s_eq[tid]=eq[bh*Nn+n0+tid];
    __syncthreads();
    float mx=-3.0e38f, s=0.f;
    if(orient==1){
        unsigned w=0;
        for(int nn=0;nn<128;nn++){
            int n=n0+nn;
            if((n&31)==0) w=bb[(size_t)m*bld+(n>>5)];
            if((w>>(n&31))&1u){ float v=s_eq[nn]+ekv; v=fmaxf(v,0.2f*v); mx=fmaxf(mx,v); }
        }
        for(int nn=0;nn<128;nn++){
            int n=n0+nn;
            if((n&31)==0) w=bb[(size_t)m*bld+(n>>5)];
            if((w>>(n&31))&1u){ float v=s_eq[nn]+ekv; v=fmaxf(v,0.2f*v); s+=__expf(v-mx); }
        }
    } else {
        int mw=m>>5, msh=m&31;
        for(int nn=0;nn<128;nn++){
            if((bb[(size_t)(n0+nn)*bld+mw]>>msh)&1u){ float v=s_eq[nn]+ekv; v=fmaxf(v,0.2f*v); mx=fmaxf(mx,v); }
        }
        for(int nn=0;nn<128;nn++){
            if((bb[(size_t)(n0+nn)*bld+mw]>>msh)&1u){ float v=s_eq[nn]+ekv; v=fmaxf(v,0.2f*v); s+=__expf(v-mx); }
        }
    }
    pmax[(size_t)(bh*Mm+m)*nch+chunk]=mx;
    psum[(size_t)(bh*Mm+m)*nch+chunk]=s;
}
__global__ void colmerge_k(const float* __restrict__ pmax, const float* __restrict__ psum,
                           float* __restrict__ cmax, float* __restrict__ cscale, int Mm, int nch){
    int idx=blockIdx.x*256+threadIdx.x; if(idx>=NB*HH*Mm) return;
    float mx=-3.0e38f;
    for(int c=0;c<nch;c++) mx=fmaxf(mx,pmax[(size_t)idx*nch+c]);
    float s=0.f;
    for(int c=0;c<nch;c++){
        float pm=pmax[(size_t)idx*nch+c];
        if(pm>-1.0e38f) s+=psum[(size_t)idx*nch+c]*__expf(pm-mx);
    }
    cmax[idx]=mx; cscale[idx]=(s>0.f)?(1.f/s):0.f;
}
__global__ void pgen_k(const float* __restrict__ eq, const float* __restrict__ ek,
                       const float* __restrict__ cmax, const float* __restrict__ cscale,
                       const unsigned* __restrict__ bits, float* __restrict__ P,
                       int Nn, int Mm, int orient, int bld){
    size_t idx=(size_t)blockIdx.x*256+threadIdx.x;
    if(idx>=(size_t)NB*HH*Nn*Mm) return;
    int m=(int)(idx%Mm); size_t r=idx/Mm;
    int n=(int)(r%Nn); int bh=(int)(r/Nn); int b=bh/HH;
    const unsigned* bb=bits+(size_t)b*NG*bld;
    unsigned bit;
    if(orient==1) bit=(bb[(size_t)m*bld+(n>>5)]>>(n&31))&1u;
    else          bit=(bb[(size_t)n*bld+(m>>5)]>>(m&31))&1u;
    float v=0.f;
    if(bit){
        float e=eq[bh*Nn+n]+ek[bh*Mm+m]; e=fmaxf(e,0.2f*e);
        v=__expf(e-cmax[bh*Mm+m])*cscale[bh*Mm+m];
    }
    P[idx]=v;
}

// ============ bf16-split mma.sync GEMM ============
struct GP {
    int M,N,K1,K2,Hdiv;
    const float *A1,*B1,*A2,*B2;
    int lda1,ldb1,lda2,ldb2,ldc;
    float* C;
    const float *E1,*E2;
    long long sA_b,sA_h,sB_b,sB_h,sC_b,sC_h;
    const unsigned* bits; int bld; long long sBits_b;
};
__device__ __forceinline__ void mma16816(float* c, const unsigned* a, const unsigned* b){
    asm volatile("mma.sync.aligned.m16n8k16.row.col.f32.bf16.bf16.f32 "
        "{%0,%1,%2,%3},{%4,%5,%6,%7},{%8,%9},{%0,%1,%2,%3};"
        : "+f"(c[0]),"+f"(c[1]),"+f"(c[2]),"+f"(c[3])
        : "r"(a[0]),"r"(a[1]),"r"(a[2]),"r"(a[3]),"r"(b[0]),"r"(b[1]));
}
// smem layout per buffer (bf16 elems): Ah[128*40] Al[128*40] Bh[64*40] Bl[64*40]
constexpr int PAD=40, APL=128*PAD, BPL=64*PAD, SSTR=2*APL+2*BPL; // 15360 elems
constexpr int SMB=2*SSTR*2; // bytes = 61440

template<int EPI>
__device__ __forceinline__ void epi_pair(float x0,float x1,float* cp,const float* e1,const float* e2){
    float2 o;
    if(EPI==0){ o.x=x0; o.y=x1; }
    else if(EPI==2){
        o.x=x0>0.f?x0:__expf(x0)-1.f; o.y=x1>0.f?x1:__expf(x1)-1.f;
    } else {
        float2 v1=*(const float2*)e1, v2=*(const float2*)e2; float f;
        f=1.f/(1.f+__expf(-x0)); o.x=v2.x+f*(v1.x-v2.x);
        f=1.f/(1.f+__expf(-x1)); o.y=v2.y+f*(v1.y-v2.y);
    }
    *(float2*)cp=o;
}

template<int ASRC,int EPI>
__global__ void __launch_bounds__(256) gemm_k(GP p){
    extern __shared__ __nv_bfloat16 sm[];
    const int t=threadIdx.x, lane=t&31, wid=t>>5;
    const int wm=wid&3, wn=wid>>2, g=lane>>2, tc=lane&3;
    const int m0=blockIdx.x*128, n0=blockIdx.y*64, z=blockIdx.z;
    const int zb=z/p.Hdiv, zh=z%p.Hdiv;
    const float* B1=p.B1+zb*p.sB_b+zh*p.sB_h;
    float* C=p.C+zb*p.sC_b+zh*p.sC_h;
    const float* A1=nullptr; const unsigned* bitsp=nullptr;
    if(ASRC==0) A1=p.A1+zb*p.sA_b+zh*p.sA_h;
    else        bitsp=p.bits+zb*p.sBits_b;
    const int Ktot=p.K1+p.K2, niter=Ktot>>5;
    float acc[2][4][4]={};
    // staging regs
    float rA[16], rB[8]; unsigned rW=0;
    const int ar=t>>1, akq=(t&1)*16;        // A: row, k-quarter
    const int br=t>>3, bnq=(t&7)*8;         // B: k-row, n-offset
    const int wk=t&31, wsel=t>>5;           // bit path

    auto loadregs=[&](int it){
        int kk=it<<5;
        if(ASRC==0){
            const float* Ap; int ldA,ko;
            if(kk<p.K1){Ap=A1; ldA=p.lda1; ko=kk;} else {Ap=p.A2; ldA=p.lda2; ko=kk-p.K1;}
            const float* s=Ap+(long long)(m0+ar)*ldA+ko+akq;
            #pragma unroll
            for(int q=0;q<4;q++) *(float4*)(rA+q*4)=*(const float4*)(s+q*4);
        } else {
            rW=bitsp[(long long)(kk+wk)*p.bld+((unsigned)m0>>5)+(wsel>>1)];
        }
        const float* Bp; int ldB,ko;
        if(kk<p.K1){Bp=B1; ldB=p.ldb1; ko=kk;} else {Bp=p.B2; ldB=p.ldb2; ko=kk-p.K1;}
        const float* s=Bp+(long long)(ko+br)*ldB+n0+bnq;
        *(float4*)(rB)=*(const float4*)(s);
        *(float4*)(rB+4)=*(const float4*)(s+4);
    };
    auto storesm=[&](int buf){
        __nv_bfloat16* Ah=sm+buf*SSTR; __nv_bfloat16* Al=Ah+APL;
        __nv_bfloat16* Bh=Ah+2*APL;    __nv_bfloat16* Bl=Bh+BPL;
        if(ASRC==0){
            #pragma unroll
            for(int i=0;i<16;i+=2){
                float x0=rA[i], x1=rA[i+1];
                __nv_bfloat16 h0=__float2bfloat16_rn(x0), h1=__float2bfloat16_rn(x1);
                __nv_bfloat16 l0=__float2bfloat16_rn(x0-__bfloat162float(h0));
                __nv_bfloat16 l1=__float2bfloat16_rn(x1-__bfloat162float(h1));
                int o=ar*PAD+akq+i;
                *(__nv_bfloat162*)(Ah+o)=__nv_bfloat162(h0,h1);
                *(__nv_bfloat162*)(Al+o)=__nv_bfloat162(l0,l1);
            }
        } else {
            int mb=wsel*16, sh=(wsel&1)*16;
            #pragma unroll
            for(int i=0;i<16;i++)
                Ah[(mb+i)*PAD+wk]=__float2bfloat16_rn((float)((rW>>(sh+i))&1u));
        }
        #pragma unroll
        for(int i=0;i<8;i++){
            float x=rB[i];
            __nv_bfloat16 h=__float2bfloat16_rn(x);
            Bh[(bnq+i)*PAD+br]=h;
            Bl[(bnq+i)*PAD+br]=__float2bfloat16_rn(x-__bfloat162float(h));
        }
    };

    loadregs(0);
    for(int it=0;it<niter;it++){
        int buf=it&1;
        storesm(buf);
        __syncthreads();
        if(it+1<niter) loadregs(it+1);
        __nv_bfloat16* Ah=sm+buf*SSTR; __nv_bfloat16* Al=Ah+APL;
        __nv_bfloat16* Bh=Ah+2*APL;    __nv_bfloat16* Bl=Bh+BPL;
        #pragma unroll
        for(int ks=0;ks<32;ks+=16){
            unsigned aH[2][4], aL[2][4], bH[4][2], bL[4][2];
            #pragma unroll
            for(int mt=0;mt<2;mt++){
                int r=(wm*32+mt*16+g)*PAD+ks+tc*2;
                aH[mt][0]=*(unsigned*)(Ah+r);        aH[mt][1]=*(unsigned*)(Ah+r+8*PAD);
                aH[mt][2]=*(unsigned*)(Ah+r+8);      aH[mt][3]=*(unsigned*)(Ah+r+8*PAD+8);
                if(ASRC==0){
                aL[mt][0]=*(unsigned*)(Al+r);        aL[mt][1]=*(unsigned*)(Al+r+8*PAD);
                aL[mt][2]=*(unsigned*)(Al+r+8);      aL[mt][3]=*(unsigned*)(Al+r+8*PAD+8); }
            }
            #pragma unroll
            for(int nt=0;nt<4;nt++){
                int r=(wn*32+nt*8+g)*PAD+ks+tc*2;
                bH[nt][0]=*(unsigned*)(Bh+r); bH[nt][1]=*(unsigned*)(Bh+r+8);
                bL[nt][0]=*(unsigned*)(Bl+r); bL[nt][1]=*(unsigned*)(Bl+r+8);
            }
            #pragma unroll
            for(int mt=0;mt<2;mt++)
                #pragma unroll
                for(int nt=0;nt<4;nt++){
                    mma16816(acc[mt][nt],aH[mt],bH[nt]);
                    mma16816(acc[mt][nt],aH[mt],bL[nt]);
                    if(ASRC==0) mma16816(acc[mt][nt],aL[mt],bH[nt]);
                }
        }
        __syncthreads();
    }
    #pragma unroll
    for(int mt=0;mt<2;mt++)
        #pragma unroll
        for(int nt=0;nt<4;nt++){
            long long r0=m0+wm*32+mt*16+g;
            int col=n0+wn*32+nt*8+tc*2;
            float* cp0=C+r0*p.ldc+col; float* cp1=C+(r0+8)*p.ldc+col;
            const float *e10=nullptr,*e20=nullptr,*e11=nullptr,*e21=nullptr;
            if(EPI==1){
                e10=p.E1+r0*p.ldc+col; e20=p.E2+r0*p.ldc+col;
                e11=p.E1+(r0+8)*p.ldc+col; e21=p.E2+(r0+8)*p.ldc+col;
            }
            epi_pair<EPI>(acc[mt][nt][0],acc[mt][nt][1],cp0,e10,e20);
            epi_pair<EPI>(acc[mt][nt][2],acc[mt][nt][3],cp1,e11,e21);
        }
}

static void gemm_go(int asrc,int epi,const GP& p,int zc){
    dim3 g(p.M/128,p.N/64,zc);
    if(asrc==1)      gemm_k<1,0><<<g,256,SMB>>>(p);
    else if(epi==0)  gemm_k<0,0><<<g,256,SMB>>>(p);
    else if(epi==1)  gemm_k<0,1><<<g,256,SMB>>>(p);
    else             gemm_k<0,2><<<g,256,SMB>>>(p);
}
static void proj_go(const float* X,int rows,const float* Wt,float* out){
    GP p{}; p.M=rows; p.N=512; p.K1=512; p.Hdiv=1;
    p.A1=X; p.lda1=512; p.B1=Wt; p.ldb1=512; p.C=out; p.ldc=512;
    gemm_go(0,0,p,1);
}
static void fusion_go(const float* a,const float* bm,int rows,const float* W,const float* U,
                      const float* Wf,const float* Uf,float* P1,float* out){
    GP p{}; p.M=rows; p.N=512; p.K1=512; p.K2=512; p.Hdiv=1;
    p.A1=a; p.lda1=512; p.B1=W; p.ldb1=512;
    p.A2=bm; p.lda2=512; p.B2=U; p.ldb2=512;
    p.C=P1; p.ldc=512;
    gemm_go(0,0,p,1);
    p.B1=Wf; p.B2=Uf; p.C=out; p.E1=P1; p.E2=a;
    gemm_go(0,1,p,1);
}
static void attn_go(float* S,const float* q,int Nqq,const float* kv,int Nkv,
                    const float* Wt,const float* a1,const float* a2,
                    int orient,const unsigned* bits,int bld,float* agg){
    float *projQ=S+O_PJQ,*projK=S+O_PJK,*eq=S+O_EQ,*ek=S+O_EK;
    float *cm=S+O_CM,*cs=S+O_CS,*pm=S+O_PM,*ps=S+O_PS,*P=S+O_PB;
    proj_go(q,NB*Nqq,Wt,projQ);
    proj_go(kv,NB*Nkv,Wt,projK);
    dot_a_k<<<(NB*HH*Nqq+255)/256,256>>>(projQ,a1,eq,Nqq);
    dot_a_k<<<(NB*HH*Nkv+255)/256,256>>>(projK,a2,ek,Nkv);
    int nch=Nqq/128;
    { dim3 g(Nkv/128,nch,NB*HH); colstats_k<<<g,128>>>(eq,ek,bits,pm,ps,Nqq,Nkv,nch,orient,bld); }
    colmerge_k<<<(NB*HH*Nkv+255)/256,256>>>(pm,ps,cm,cs,Nkv,nch);
    { size_t tot=(size_t)NB*HH*Nqq*Nkv;
      pgen_k<<<(unsigned)((tot+255)/256),256>>>(eq,ek,cm,cs,bits,P,Nqq,Nkv,orient,bld); }
    GP p{}; p.M=Nqq; p.N=64; p.K1=Nkv; p.Hdiv=HH;
    p.A1=P; p.lda1=Nkv; p.sA_b=(long long)HH*Nqq*Nkv; p.sA_h=(long long)Nqq*Nkv;
    p.B1=projK; p.ldb1=512; p.sB_b=(long long)Nkv*512; p.sB_h=64;
    p.C=agg; p.ldc=512; p.sC_b=(long long)Nqq*512; p.sC_h=64;
    gemm_go(0,2,p,NB*HH);
}

extern "C" void kernel_launch(void* const* d_in, const int* in_sizes, int n_in,
                              void* d_out, int out_size){
    cudaFuncSetAttribute(gemm_k<0,0>,cudaFuncAttributeMaxDynamicSharedMemorySize,SMB);
    cudaFuncSetAttribute(gemm_k<0,1>,cudaFuncAttributeMaxDynamicSharedMemorySize,SMB);
    cudaFuncSetAttribute(gemm_k<0,2>,cudaFuncAttributeMaxDynamicSharedMemorySize,SMB);
    cudaFuncSetAttribute(gemm_k<1,0>,cudaFuncAttributeMaxDynamicSharedMemorySize,SMB);
    float* S; cudaGetSymbolAddress((void**)&S, d_scratch);
    const float* in_g=(const float*)d_in[0];
    const float* in_c=(const float*)d_in[1];
    const float* in_q=(const float*)d_in[2];
    const int* adj_gc=(const int*)d_in[3];
    const int* adj_gq=(const int*)d_in[4];
    const float* aW[3]={(const float*)d_in[5],(const float*)d_in[8],(const float*)d_in[11]};
    const float* aa1[3]={(const float*)d_in[6],(const float*)d_in[9],(const float*)d_in[12]};
    const float* aa2[3]={(const float*)d_in[7],(const float*)d_in[10],(const float*)d_in[13]};
    const float* fW=(const float*)d_in[14];
    const float* fU=(const float*)d_in[15];
    const float* fWf=(const float*)d_in[16];
    const float* fUf=(const float*)d_in[17];
    float* out=(float*)d_out;

    unsigned* bgc=(unsigned*)(S+O_BGC);
    unsigned* bgq=(unsigned*)(S+O_BGQ);
    float* Wt=S+O_WT;
    float *gsame=S+O_GS, *agg=S+O_AGG, *P1=S+O_P1, *G1tmp=S+O_G1;

    bitpack_k<<<512,256>>>(adj_gc,bgc,131072);
    bitpack_k<<<128,256>>>(adj_gq,bgq,32768);
    for(int tp=0;tp<3;tp++)
        repack_k<<<2048,256>>>(aW[tp],Wt+(size_t)tp*2*FF*512,2*HH*FF*DD);

    for(int l=0;l<2;l++){
        const float *Gin,*Cin,*Qin; float *Gout,*Cout,*Qout;
        if(l==0){ Gin=in_g; Cin=in_c; Qin=in_q; Gout=S+O_G0; Cout=S+O_C0; Qout=S+O_Q0; }
        else    { Gin=S+O_G0; Cin=S+O_C0; Qin=S+O_Q0;
                  Gout=out; Cout=out+SZ_GF; Qout=out+2*SZ_GF; }
        const float* fWl=fW+(size_t)l*4*FF*FF;  const float* fUl=fU+(size_t)l*4*FF*FF;
        const float* fWfl=fWf+(size_t)l*4*FF*FF; const float* fUfl=fUf+(size_t)l*4*FF*FF;
        {
            GP p{}; p.M=NC; p.N=512; p.K1=NG; p.Hdiv=1;
            p.bits=bgc; p.bld=NC/32; p.sBits_b=(long long)NG*(NC/32);
            p.B1=Gin; p.ldb1=512; p.sB_b=(long long)NG*512;
            p.C=gsame; p.ldc=512; p.sC_b=(long long)NC*512;
            gemm_go(1,0,p,NB);
        }
        fusion_go(Cin,gsame,NB*NC, fWl+0*FF*FF,fUl+0*FF*FF,fWfl+0*FF*FF,fUfl+0*FF*FF, P1,Cout);
        attn_go(S,Gin,NG,Cin,NC, Wt+(size_t)(0*2+l)*FF*512, aa1[0]+l*HH*DD, aa2[0]+l*HH*DD, 0,bgc,NC/32, agg);
        fusion_go(Gin,agg,NB*NG, fWl+1*FF*FF,fUl+1*FF*FF,fWfl+1*FF*FF,fUfl+1*FF*FF, P1,G1tmp);
        attn_go(S,Qin,NQ,Gin,NG, Wt+(size_t)(1*2+l)*FF*512, aa1[1]+l*HH*DD, aa2[1]+l*HH*DD, 1,bgq,NQ/32, agg);
        fusion_go(Qin,agg,NB*NQ, fWl+2*FF*FF,fUl+2*FF*FF,fWfl+2*FF*FF,fUfl+2*FF*FF, P1,Qout);
        attn_go(S,Gin,NG,Qin,NQ, Wt+(size_t)(2*2+l)*FF*512, aa1[2]+l*HH*DD, aa2[2]+l*HH*DD, 0,bgq,NQ/32, agg);
        fusion_go(G1tmp,agg,NB*NG, fWl+3*FF*FF,fUl+3*FF*FF,fWfl+3*FF*FF,fUfl+3*FF*FF, P1,Gout);
    }
}